// round 1
// baseline (speedup 1.0000x reference)
#include <cuda_runtime.h>

typedef unsigned long long u64;
typedef unsigned int u32;

constexpr int NB = 32, NC = 64, NH = 112, NW = 112;
constexpr int HW = NH * NW;              // 12544
constexpr int SEGROW = NW / 4;           // 28
constexpr int NSEG = NB * NH * SEGROW;   // 100352
constexpr int TPB = 128;
constexpr int NBLK = NSEG / TPB;         // 784
constexpr float kALPHA = 0.25f;

// scratch (static device globals; no dynamic allocation)
__device__ u64 g_bits1[NB * HW];
__device__ u64 g_bits2[NB * HW];
__device__ float g_out1[(size_t)NB * NC * HW];
__device__ u64 g_wb[2][NC][9];
__device__ int g_corr[2][NC][9];
__device__ float g_scale[2][NC];

// ---------------------------------------------------------------------------
// Weight prep: per output channel o of each conv:
//   scale[o] = mean(|w|) over (in,kh,kw)
//   wbits[o][tap] : bit i = (w[o][i][tap] >= 0)
//   corr[o][tap]  = 64 - 2*popc(wbits)   (contribution of a zero word)
// grid: (64, 2), block: 64 threads (thread = input channel)
// ---------------------------------------------------------------------------
__global__ void prep_weights_kernel(const float* __restrict__ w3,
                                    const float* __restrict__ wpw) {
    int o = blockIdx.x;
    int cv = blockIdx.y;
    const float* w = cv ? wpw : w3;
    int i = threadIdx.x;
    int lane = i & 31, warp = i >> 5;
    const float* wrow = w + (size_t)(o * NC + i) * 9;
    float wv[9];
    float s = 0.f;
#pragma unroll
    for (int t = 0; t < 9; t++) { wv[t] = wrow[t]; s += fabsf(wv[t]); }
    __shared__ u32 sb[2][9];
#pragma unroll
    for (int t = 0; t < 9; t++) {
        u32 m = __ballot_sync(0xffffffffu, wv[t] >= 0.f);
        if (lane == 0) sb[warp][t] = m;
    }
#pragma unroll
    for (int off = 16; off > 0; off >>= 1)
        s += __shfl_down_sync(0xffffffffu, s, off);
    __shared__ float ssum[2];
    if (lane == 0) ssum[warp] = s;
    __syncthreads();
    if (i == 0) g_scale[cv][o] = (ssum[0] + ssum[1]) * (1.0f / 576.0f);
    if (i < 9) {
        u64 wb = ((u64)sb[1][i] << 32) | (u64)sb[0][i];
        g_wb[cv][o][i] = wb;
        g_corr[cv][o][i] = 64 - 2 * __popcll(wb);
    }
}

// ---------------------------------------------------------------------------
// Pack sign(x + b11) into 64-bit channel words. Thread = 4 consecutive pixels.
// ---------------------------------------------------------------------------
__global__ void __launch_bounds__(TPB)
pack_input_kernel(const float* __restrict__ x, const float* __restrict__ b11) {
    __shared__ float sb[NC];
    int tid = threadIdx.x;
    if (tid < NC) sb[tid] = b11[tid];
    __syncthreads();
    int seg = blockIdx.x * TPB + tid;
    int b = seg / (NH * SEGROW);
    int r = seg % (NH * SEGROW);
    int y = r / SEGROW;
    int sx = (r % SEGROW) * 4;
    const float* xp = x + (size_t)b * NC * HW + y * NW + sx;
    u32 lo0 = 0, lo1 = 0, lo2 = 0, lo3 = 0;
    u32 hi0 = 0, hi1 = 0, hi2 = 0, hi3 = 0;
#pragma unroll
    for (int c = 0; c < 32; c++) {
        float4 v = *(const float4*)(xp + (size_t)c * HW);
        float bb = sb[c];
        u32 bit = 1u << c;
        if (v.x + bb >= 0.f) lo0 |= bit;
        if (v.y + bb >= 0.f) lo1 |= bit;
        if (v.z + bb >= 0.f) lo2 |= bit;
        if (v.w + bb >= 0.f) lo3 |= bit;
    }
#pragma unroll
    for (int c = 32; c < 64; c++) {
        float4 v = *(const float4*)(xp + (size_t)c * HW);
        float bb = sb[c];
        u32 bit = 1u << (c - 32);
        if (v.x + bb >= 0.f) hi0 |= bit;
        if (v.y + bb >= 0.f) hi1 |= bit;
        if (v.z + bb >= 0.f) hi2 |= bit;
        if (v.w + bb >= 0.f) hi3 |= bit;
    }
    u64* op = g_bits1 + (size_t)b * HW + y * NW + sx;
    ulonglong2* ov = (ulonglong2*)op;
    ov[0] = make_ulonglong2(((u64)hi0 << 32) | lo0, ((u64)hi1 << 32) | lo1);
    ov[1] = make_ulonglong2(((u64)hi2 << 32) | lo2, ((u64)hi3 << 32) | lo3);
}

// ---------------------------------------------------------------------------
// Binary 3x3 conv via XOR+POPC, fully fused epilogue.
// CV==0: conv1: out1 = prelu(x + a*conv + b12, a1) + b13 -> g_out1,
//        and bitpack sign(out1 + b21) -> g_bits2.
// CV==1: conv2: out2 = prelu(a*conv + out1 + b22, a2) + b23 -> dout.
// Thread = 4 consecutive pixels x all 64 output channels.
// ---------------------------------------------------------------------------
template <int CV>
__global__ void __launch_bounds__(TPB)
bconv_kernel(const float* __restrict__ xin, float* __restrict__ dout,
             const float* __restrict__ bA, const float* __restrict__ sl_,
             const float* __restrict__ bB, const float* __restrict__ bS) {
    __shared__ u64 s_wb[NC][10];   // padded row for alignment
    __shared__ int s_corr[NC][9];
    __shared__ float s_as[NC], s_bA[NC], s_sl[NC], s_bB[NC], s_bS[NC];
    int tid = threadIdx.x;
    for (int k = tid; k < NC * 9; k += TPB) {
        int o = k / 9, t = k - o * 9;
        s_wb[o][t] = g_wb[CV][o][t];
        s_corr[o][t] = g_corr[CV][o][t];
    }
    if (tid < NC) {
        s_as[tid] = g_scale[CV][tid] * kALPHA;
        s_bA[tid] = bA[tid];
        s_sl[tid] = sl_[tid];
        s_bB[tid] = bB[tid];
        s_bS[tid] = (CV == 0) ? bS[tid] : 0.f;
    }
    __syncthreads();

    int seg = blockIdx.x * TPB + tid;
    int b = seg / (NH * SEGROW);
    int r = seg % (NH * SEGROW);
    int y = r / SEGROW;
    int sx = (r % SEGROW) * 4;
    bool top = (y == 0), bot = (y == NH - 1);
    bool left = (sx == 0), right = (sx + 4 == NW);
    bool border = top | bot | left | right;

    const u64* bitsIn = (CV == 0) ? g_bits1 : g_bits2;
    const float* resid = (CV == 0) ? xin : g_out1;
    float* outp = (CV == 0) ? g_out1 : dout;

    // activation bit patch: 3 rows x 6 cols covers 4 output pixels; OOB -> 0
    const u64* bp = bitsIn + (size_t)b * HW;
    u64 a[3][6];
#pragma unroll
    for (int rr = 0; rr < 3; rr++) {
        int yy = y - 1 + rr;
        bool rv = (yy >= 0) && (yy < NH);
#pragma unroll
        for (int k = 0; k < 6; k++) {
            int cx = sx - 1 + k;
            a[rr][k] = (rv && cx >= 0 && cx < NW) ? __ldg(bp + yy * NW + cx) : 0ull;
        }
    }

    size_t pixbase = (size_t)b * NC * HW + (size_t)(y * NW + sx);
    u32 slo0 = 0, slo1 = 0, slo2 = 0, slo3 = 0;
    u32 shi0 = 0, shi1 = 0, shi2 = 0, shi3 = 0;

#pragma unroll 1
    for (int o = 0; o < NC; o++) {
        u64 w[9];
#pragma unroll
        for (int t = 0; t < 9; t++) w[t] = s_wb[o][t];
        int acc0 = 0, acc1 = 0, acc2 = 0, acc3 = 0;
#pragma unroll
        for (int t = 0; t < 9; t++) {
            int rr = t / 3, cc = t - rr * 3;
            u64 wt = w[t];
            acc0 += __popcll(wt ^ a[rr][cc + 0]);
            acc1 += __popcll(wt ^ a[rr][cc + 1]);
            acc2 += __popcll(wt ^ a[rr][cc + 2]);
            acc3 += __popcll(wt ^ a[rr][cc + 3]);
        }
        int cb = 0, cl = 0, cr = 0;
        if (border) {
            const int* cp = s_corr[o];
            int c0 = cp[0], c1 = cp[1], c2 = cp[2];
            int c3 = cp[3], c5 = cp[5];
            int c6 = cp[6], c7 = cp[7], c8 = cp[8];
            if (top) cb += c0 + c1 + c2;
            if (bot) cb += c6 + c7 + c8;
            if (left)  cl = c3 + (top ? 0 : c0) + (bot ? 0 : c6);
            if (right) cr = c5 + (top ? 0 : c2) + (bot ? 0 : c8);
        }
        float as = s_as[o];
        const float* rp = resid + pixbase + (size_t)o * HW;
        float4 res = *(const float4*)rp;
        float v0 = fmaf(as, (float)(576 - 2 * acc0 - cb - cl), res.x);
        float v1 = fmaf(as, (float)(576 - 2 * acc1 - cb), res.y);
        float v2 = fmaf(as, (float)(576 - 2 * acc2 - cb), res.z);
        float v3 = fmaf(as, (float)(576 - 2 * acc3 - cb - cr), res.w);
        float ba = s_bA[o], sl = s_sl[o], bb = s_bB[o];
        v0 += ba; v1 += ba; v2 += ba; v3 += ba;
        v0 = fmaxf(v0, 0.f) + sl * fminf(v0, 0.f);
        v1 = fmaxf(v1, 0.f) + sl * fminf(v1, 0.f);
        v2 = fmaxf(v2, 0.f) + sl * fminf(v2, 0.f);
        v3 = fmaxf(v3, 0.f) + sl * fminf(v3, 0.f);
        v0 += bb; v1 += bb; v2 += bb; v3 += bb;
        *(float4*)(outp + pixbase + (size_t)o * HW) = make_float4(v0, v1, v2, v3);
        if (CV == 0) {
            float bs = s_bS[o];
            u32 bit = 1u << (o & 31);
            if (o < 32) {
                if (v0 + bs >= 0.f) slo0 |= bit;
                if (v1 + bs >= 0.f) slo1 |= bit;
                if (v2 + bs >= 0.f) slo2 |= bit;
                if (v3 + bs >= 0.f) slo3 |= bit;
            } else {
                if (v0 + bs >= 0.f) shi0 |= bit;
                if (v1 + bs >= 0.f) shi1 |= bit;
                if (v2 + bs >= 0.f) shi2 |= bit;
                if (v3 + bs >= 0.f) shi3 |= bit;
            }
        }
    }
    if (CV == 0) {
        u64* op = g_bits2 + (size_t)b * HW + y * NW + sx;
        ulonglong2* ov = (ulonglong2*)op;
        ov[0] = make_ulonglong2(((u64)shi0 << 32) | slo0, ((u64)shi1 << 32) | slo1);
        ov[1] = make_ulonglong2(((u64)shi2 << 32) | slo2, ((u64)shi3 << 32) | slo3);
    }
}

extern "C" void kernel_launch(void* const* d_in, const int* in_sizes, int n_in,
                              void* d_out, int out_size) {
    const float* x   = (const float*)d_in[0];
    const float* w3  = (const float*)d_in[1];
    const float* wpw = (const float*)d_in[2];
    const float* b11 = (const float*)d_in[3];
    const float* b12 = (const float*)d_in[4];
    const float* b13 = (const float*)d_in[5];
    const float* b21 = (const float*)d_in[6];
    const float* b22 = (const float*)d_in[7];
    const float* b23 = (const float*)d_in[8];
    const float* a1  = (const float*)d_in[9];
    const float* a2  = (const float*)d_in[10];
    float* out = (float*)d_out;

    prep_weights_kernel<<<dim3(64, 2), 64>>>(w3, wpw);
    pack_input_kernel<<<NBLK, TPB>>>(x, b11);
    bconv_kernel<0><<<NBLK, TPB>>>(x, nullptr, b12, a1, b13, b21);
    bconv_kernel<1><<<NBLK, TPB>>>(nullptr, out, b22, a2, b23, nullptr);
}

// round 3
// speedup vs baseline: 1.1449x; 1.1449x over previous
#include <cuda_runtime.h>

typedef unsigned long long u64;
typedef unsigned int u32;

constexpr int NB = 32, NC = 64, NH = 112, NW = 112;
constexpr int HW = NH * NW;               // 12544
constexpr int SEGROW4 = NW / 4;           // 28 (pack kernel, 4 px/thread)
constexpr int NSEG4 = NB * NH * SEGROW4;  // 100352
constexpr int SEGROW2 = NW / 2;           // 56 (conv kernels, 2 px/thread)
constexpr int NSEG2 = NB * NH * SEGROW2;  // 200704
constexpr int TPB = 128;
constexpr int NBLK4 = NSEG4 / TPB;        // 784
constexpr int NBLK2 = NSEG2 / TPB;        // 1568
constexpr float kALPHA = 0.25f;

// scratch (static device globals; no dynamic allocation)
__device__ u64 g_bits1[NB * HW];
__device__ u64 g_bits2[NB * HW];
__device__ float g_out1[(size_t)NB * NC * HW];
__device__ u64 g_wb[2][NC][9];
__device__ int g_corr[2][NC][9];
__device__ float g_scale[2][NC];

// ---------------------------------------------------------------------------
// Weight prep: scale[o]=mean|w|, bit-packed sign words, zero-pad corrections.
// ---------------------------------------------------------------------------
__global__ void prep_weights_kernel(const float* __restrict__ w3,
                                    const float* __restrict__ wpw) {
    int o = blockIdx.x;
    int cv = blockIdx.y;
    const float* w = cv ? wpw : w3;
    int i = threadIdx.x;
    int lane = i & 31, warp = i >> 5;
    const float* wrow = w + (size_t)(o * NC + i) * 9;
    float wv[9];
    float s = 0.f;
#pragma unroll
    for (int t = 0; t < 9; t++) { wv[t] = wrow[t]; s += fabsf(wv[t]); }
    __shared__ u32 sb[2][9];
#pragma unroll
    for (int t = 0; t < 9; t++) {
        u32 m = __ballot_sync(0xffffffffu, wv[t] >= 0.f);
        if (lane == 0) sb[warp][t] = m;
    }
#pragma unroll
    for (int off = 16; off > 0; off >>= 1)
        s += __shfl_down_sync(0xffffffffu, s, off);
    __shared__ float ssum[2];
    if (lane == 0) ssum[warp] = s;
    __syncthreads();
    if (i == 0) g_scale[cv][o] = (ssum[0] + ssum[1]) * (1.0f / 576.0f);
    if (i < 9) {
        u64 wb = ((u64)sb[1][i] << 32) | (u64)sb[0][i];
        g_wb[cv][o][i] = wb;
        g_corr[cv][o][i] = 64 - 2 * __popcll(wb);
    }
}

// ---------------------------------------------------------------------------
// Pack sign(x + b11) into 64-bit channel words. Thread = 4 consecutive pixels.
// ---------------------------------------------------------------------------
__global__ void __launch_bounds__(TPB)
pack_input_kernel(const float* __restrict__ x, const float* __restrict__ b11) {
    __shared__ float sb[NC];
    int tid = threadIdx.x;
    if (tid < NC) sb[tid] = b11[tid];
    __syncthreads();
    int seg = blockIdx.x * TPB + tid;
    int b = seg / (NH * SEGROW4);
    int r = seg % (NH * SEGROW4);
    int y = r / SEGROW4;
    int sx = (r % SEGROW4) * 4;
    const float* xp = x + (size_t)b * NC * HW + y * NW + sx;
    u32 lo0 = 0, lo1 = 0, lo2 = 0, lo3 = 0;
    u32 hi0 = 0, hi1 = 0, hi2 = 0, hi3 = 0;
#pragma unroll
    for (int c = 0; c < 32; c++) {
        float4 v = *(const float4*)(xp + (size_t)c * HW);
        float bb = sb[c];
        u32 bit = 1u << c;
        if (v.x + bb >= 0.f) lo0 |= bit;
        if (v.y + bb >= 0.f) lo1 |= bit;
        if (v.z + bb >= 0.f) lo2 |= bit;
        if (v.w + bb >= 0.f) lo3 |= bit;
    }
#pragma unroll
    for (int c = 32; c < 64; c++) {
        float4 v = *(const float4*)(xp + (size_t)c * HW);
        float bb = sb[c];
        u32 bit = 1u << (c - 32);
        if (v.x + bb >= 0.f) hi0 |= bit;
        if (v.y + bb >= 0.f) hi1 |= bit;
        if (v.z + bb >= 0.f) hi2 |= bit;
        if (v.w + bb >= 0.f) hi3 |= bit;
    }
    u64* op = g_bits1 + (size_t)b * HW + y * NW + sx;
    ulonglong2* ov = (ulonglong2*)op;
    ov[0] = make_ulonglong2(((u64)hi0 << 32) | lo0, ((u64)hi1 << 32) | lo1);
    ov[1] = make_ulonglong2(((u64)hi2 << 32) | lo2, ((u64)hi3 << 32) | lo3);
}

// ---------------------------------------------------------------------------
// Binary 3x3 conv via XOR+POPC, fully fused epilogue.
// Thread = 2 consecutive pixels x all 64 output channels.
// Residual load software-pipelined (prefetch o+1 while computing o).
// CV==0: out1 = prelu(x + a*conv + b12, a1) + b13 -> g_out1, bitpack -> g_bits2
// CV==1: out2 = prelu(a*conv + out1 + b22, a2) + b23 -> dout
// ---------------------------------------------------------------------------
template <int CV>
__global__ void __launch_bounds__(TPB)
bconv_kernel(const float* __restrict__ xin, float* __restrict__ dout,
             const float* __restrict__ bA, const float* __restrict__ sl_,
             const float* __restrict__ bB, const float* __restrict__ bS) {
    __shared__ u64 s_wb[NC][10];   // padded row
    __shared__ int s_corr[NC][9];
    __shared__ float s_as[NC], s_bA[NC], s_sl[NC], s_bB[NC], s_bS[NC];
    int tid = threadIdx.x;
    for (int k = tid; k < NC * 9; k += TPB) {
        int o = k / 9, t = k - o * 9;
        s_wb[o][t] = g_wb[CV][o][t];
        s_corr[o][t] = g_corr[CV][o][t];
    }
    if (tid < NC) {
        s_as[tid] = g_scale[CV][tid] * kALPHA;
        s_bA[tid] = bA[tid];
        s_sl[tid] = sl_[tid];
        s_bB[tid] = bB[tid];
        s_bS[tid] = (CV == 0) ? bS[tid] : 0.f;
    }
    __syncthreads();

    int seg = blockIdx.x * TPB + tid;
    int b = seg / (NH * SEGROW2);
    int r = seg % (NH * SEGROW2);
    int y = r / SEGROW2;
    int sx = (r % SEGROW2) * 2;
    bool top = (y == 0), bot = (y == NH - 1);
    bool left = (sx == 0), right = (sx + 2 == NW);
    bool border = top | bot | left | right;

    const u64* bitsIn = (CV == 0) ? g_bits1 : g_bits2;
    const float* resid = (CV == 0) ? xin : g_out1;
    float* outp = (CV == 0) ? g_out1 : dout;

    // activation bit patch: 3 rows x 4 cols covers 2 output pixels; OOB -> 0
    const u64* bp = bitsIn + (size_t)b * HW;
    u64 a[3][4];
#pragma unroll
    for (int rr = 0; rr < 3; rr++) {
        int yy = y - 1 + rr;
        bool rv = (yy >= 0) && (yy < NH);
#pragma unroll
        for (int k = 0; k < 4; k++) {
            int cx = sx - 1 + k;
            a[rr][k] = (rv && cx >= 0 && cx < NW) ? __ldg(bp + yy * NW + cx) : 0ull;
        }
    }

    size_t pixbase = (size_t)b * NC * HW + (size_t)(y * NW + sx);
    const float* rp = resid + pixbase;
    float* op = outp + pixbase;

    u32 slo0 = 0, slo1 = 0, shi0 = 0, shi1 = 0;

    float2 res = *(const float2*)rp;   // o = 0 residual

#pragma unroll 1
    for (int o = 0; o < NC; o++) {
        // prefetch next residual (clamped, branch-free)
        int onx = (o < NC - 1) ? o + 1 : o;
        float2 res_nxt = *(const float2*)(rp + (size_t)onx * HW);

        int acc0 = 0, acc1 = 0;
#pragma unroll
        for (int t = 0; t < 9; t++) {
            int rr = t / 3, cc = t - rr * 3;
            u64 wt = s_wb[o][t];
            acc0 += __popcll(wt ^ a[rr][cc + 0]);
            acc1 += __popcll(wt ^ a[rr][cc + 1]);
        }
        int cb = 0, cl = 0, cr = 0;
        if (border) {
            const int* cp = s_corr[o];
            int c0 = cp[0], c1 = cp[1], c2 = cp[2];
            int c3 = cp[3], c5 = cp[5];
            int c6 = cp[6], c7 = cp[7], c8 = cp[8];
            if (top) cb += c0 + c1 + c2;
            if (bot) cb += c6 + c7 + c8;
            if (left)  cl = c3 + (top ? 0 : c0) + (bot ? 0 : c6);
            if (right) cr = c5 + (top ? 0 : c2) + (bot ? 0 : c8);
        }
        float as = s_as[o];
        float v0 = fmaf(as, (float)(576 - 2 * acc0 - cb - cl), res.x);
        float v1 = fmaf(as, (float)(576 - 2 * acc1 - cb - cr), res.y);
        float ba = s_bA[o], sl = s_sl[o], bb = s_bB[o];
        v0 += ba; v1 += ba;
        v0 = fmaxf(v0, 0.f) + sl * fminf(v0, 0.f);
        v1 = fmaxf(v1, 0.f) + sl * fminf(v1, 0.f);
        v0 += bb; v1 += bb;
        *(float2*)(op + (size_t)o * HW) = make_float2(v0, v1);
        if (CV == 0) {
            float bs = s_bS[o];
            u32 bit = 1u << (o & 31);
            if (o < 32) {
                if (v0 + bs >= 0.f) slo0 |= bit;
                if (v1 + bs >= 0.f) slo1 |= bit;
            } else {
                if (v0 + bs >= 0.f) shi0 |= bit;
                if (v1 + bs >= 0.f) shi1 |= bit;
            }
        }
        res = res_nxt;
    }
    if (CV == 0) {
        u64* obp = g_bits2 + (size_t)b * HW + y * NW + sx;
        *(ulonglong2*)obp =
            make_ulonglong2(((u64)shi0 << 32) | slo0, ((u64)shi1 << 32) | slo1);
    }
}

extern "C" void kernel_launch(void* const* d_in, const int* in_sizes, int n_in,
                              void* d_out, int out_size) {
    const float* x   = (const float*)d_in[0];
    const float* w3  = (const float*)d_in[1];
    const float* wpw = (const float*)d_in[2];
    const float* b11 = (const float*)d_in[3];
    const float* b12 = (const float*)d_in[4];
    const float* b13 = (const float*)d_in[5];
    const float* b21 = (const float*)d_in[6];
    const float* b22 = (const float*)d_in[7];
    const float* b23 = (const float*)d_in[8];
    const float* a1  = (const float*)d_in[9];
    const float* a2  = (const float*)d_in[10];
    float* out = (float*)d_out;

    prep_weights_kernel<<<dim3(64, 2), 64>>>(w3, wpw);
    pack_input_kernel<<<NBLK4, TPB>>>(x, b11);
    bconv_kernel<0><<<NBLK2, TPB>>>(x, nullptr, b12, a1, b13, b21);
    bconv_kernel<1><<<NBLK2, TPB>>>(nullptr, out, b22, a2, b23, nullptr);
}